// round 17
// baseline (speedup 1.0000x reference)
#include <cuda_runtime.h>
#include <math.h>

// Problem shape (fixed per reference): h is (32, 4096, 1024) fp32.
#define BATCH   32
#define SEQ     4096
#define HID     1024
#define W       32          // window rows
#define WSTART  2032        // 4096/2 - 16
#define NCH     8           // d-chunks
#define CHUNK   128         // HID / NCH
#define CPAD    132         // chunk pad: 132 % 32 == 4 -> conflict-free f4
#define NPAIR   528         // 32*33/2 upper-triangle incl diag
#define FULLM   0xFFFFFFFFu

// Scratch: per-batch, per-chunk partial Gram (upper triangle), fp32.
__device__ float g_part[BATCH][NCH][NPAIR];

// ---------------------------------------------------------------------------
// Kernel 1: partial raw Gram R = W W^T over a 128-column chunk.
// grid = (NCH, BATCH), block = 544. float4 smem path (pad 132).
// ---------------------------------------------------------------------------
__global__ void __launch_bounds__(544) gram_kernel(const float* __restrict__ h) {
    const int chunk = blockIdx.x;
    const int b     = blockIdx.y;
    __shared__ __align__(16) float As[W][CPAD];

    const int tid = threadIdx.x;
    const float* base = h + ((size_t)b * SEQ + WSTART) * HID + (size_t)chunk * CHUNK;

    for (int idx = tid; idx < W * (CHUNK / 4); idx += blockDim.x) {
        int row = idx >> 5;
        int c4  = idx & 31;
        float4 v = *(const float4*)(base + (size_t)row * HID + c4 * 4);
        reinterpret_cast<float4*>(As[row])[c4] = v;
    }
    __syncthreads();

    if (tid < NPAIR) {
        int i = 0, rem = tid;
        while (rem >= W - i) { rem -= W - i; i++; }
        int j = i + rem;

        const float4* ai = reinterpret_cast<const float4*>(As[i]);
        const float4* aj = reinterpret_cast<const float4*>(As[j]);
        float a0 = 0.f, a1 = 0.f, a2 = 0.f, a3 = 0.f;
        #pragma unroll
        for (int d = 0; d < CHUNK / 4; d++) {
            float4 x = ai[d];
            float4 y = aj[d];
            a0 = fmaf(x.x, y.x, a0);
            a1 = fmaf(x.y, y.y, a1);
            a2 = fmaf(x.z, y.z, a2);
            a3 = fmaf(x.w, y.w, a3);
        }
        g_part[b][chunk][tid] = (a0 + a1) + (a2 + a3);
    }
}

// ---------------------------------------------------------------------------
// Helpers
// ---------------------------------------------------------------------------
__device__ __forceinline__ float wsum32(float v) {
    #pragma unroll
    for (int o = 16; o; o >>= 1) v += __shfl_xor_sync(FULLM, v, o);
    return v;
}
__device__ __forceinline__ float wmin32(float v) {
    #pragma unroll
    for (int o = 16; o; o >>= 1) v = fminf(v, __shfl_xor_sync(FULLM, v, o));
    return v;
}
__device__ __forceinline__ float wmax32(float v) {
    #pragma unroll
    for (int o = 16; o; o >>= 1) v = fmaxf(v, __shfl_xor_sync(FULLM, v, o));
    return v;
}

// Dynamic select a[k] (runtime k) from a static register array: SEL mux tree.
__device__ __forceinline__ float sel32(const float (&a)[32], int k) {
    float t16[16], t8[8], t4[4], t2[2];
    #pragma unroll
    for (int j = 0; j < 16; j++) t16[j] = (k & 16) ? a[j + 16] : a[j];
    #pragma unroll
    for (int j = 0; j < 8;  j++) t8[j]  = (k & 8)  ? t16[j + 8] : t16[j];
    #pragma unroll
    for (int j = 0; j < 4;  j++) t4[j]  = (k & 4)  ? t8[j + 4]  : t8[j];
    #pragma unroll
    for (int j = 0; j < 2;  j++) t2[j]  = (k & 2)  ? t4[j + 2]  : t4[j];
    return (k & 1) ? t2[1] : t2[0];
}

// Sturm count via scaled characteristic-polynomial recurrence (division-free).
__device__ __forceinline__ int sturm32(const float* __restrict__ dS,
                                       const float* __restrict__ e2S, float x) {
    const float c  = 0.0625f;            // 1/16
    const float c2 = 0.00390625f;        // 1/256
    const float cx = c * x;
    float qpp = 1.f;                     // q_0
    float qp  = fmaf(c, dS[0], -cx);     // q_1
    int cnt = (qp < 0.f) ? 1 : 0;
    #pragma unroll
    for (int j = 1; j < 32; j++) {
        float cd = fmaf(c, dS[j], -cx);
        float t  = (c2 * e2S[j - 1]) * qpp;     // off the critical chain
        float qn = fmaf(cd, qp, -t);
        cnt += ((qn < 0.f) != (qp < 0.f));
        qpp = qp; qp = qn;
        if ((j & 7) == 7) {                      // guard under/overflow
            float mag = fmaxf(fabsf(qp), fabsf(qpp));
            if (mag > 1e18f)      { qp *= 0x1p-60f; qpp *= 0x1p-60f; }
            else if (mag < 1e-18f){ qp *= 0x1p60f;  qpp *= 0x1p60f;  }
        }
    }
    return cnt;
}

// ---------------------------------------------------------------------------
// Kernel 2: per-batch. 544 threads build Gs (one __syncthreads), then warp 0
// takes over: rsum/Ssum/dinv + DIRECT register build of C rows, Householder
// tridiag (R16 structure), division-free multi-point Sturm. Trace taken from
// the tridiagonal diagonal (similarity-invariant).
// ---------------------------------------------------------------------------
__global__ void __launch_bounds__(544) eig_kernel(float* __restrict__ out, int n) {
    const int b = blockIdx.x;
    if (b >= BATCH) return;
    const int tid  = threadIdx.x;
    const int lane = tid & 31;
    const int wid  = tid >> 5;

    __shared__ __align__(16) float Gs[W][36];    // 36-pad: aligned f4 rows
    __shared__ __align__(16) float rsumSh[W];
    __shared__ __align__(16) float dinvSh[W];
    __shared__ __align__(16) float xSh[2 * W];   // double-buffered x/v vector
    __shared__ __align__(16) float pSh[W];       // p vector
    __shared__ float  dS[W];
    __shared__ float  e2S[W];
    __shared__ float  eaS[W];

    // --- reduce chunk partials (fp32), mirror to full symmetric matrix ---
    if (tid < NPAIR) {
        float g = 0.f;
        #pragma unroll
        for (int c = 0; c < NCH; c++) g += g_part[b][c][tid];
        int i = 0, rem = tid;
        while (rem >= W - i) { rem -= W - i; i++; }
        int j = i + rem;
        Gs[i][j] = g;
        Gs[j][i] = g;
    }
    __syncthreads();

    if (wid != 0) return;   // warps 1..16 retire; warp 0 owns everything else

    // ---- warp-0 prologue: rsum, Ssum, dinv, direct register build of C ----
    const float4* gr4 = reinterpret_cast<const float4*>(Gs[lane]);
    float r0 = 0.f, r1 = 0.f, r2 = 0.f, r3 = 0.f;
    #pragma unroll
    for (int c = 0; c < 8; c++) {
        float4 g = gr4[c];
        r0 += g.x; r1 += g.y; r2 += g.z; r3 += g.w;
    }
    const float rs = (r0 + r1) + (r2 + r3);
    const float Ss = wsum32(rs);
    const float Sq = Ss * (1.0f / 1024.0f);

    float diag = Gs[lane][lane];
    float di = diag - rs * (1.0f / 16.0f) + Sq;
    if (di < 0.f) di = 0.f;
    const float dv = __fdividef(1.f, sqrtf(di) + 1e-8f);

    rsumSh[lane] = rs;
    dinvSh[lane] = dv;
    __syncwarp();

    float a[32];
    {
        const float4* rs4 = reinterpret_cast<const float4*>(rsumSh);
        const float4* dv4 = reinterpret_cast<const float4*>(dinvSh);
        const float base = Sq - rs * (1.0f / 32.0f);
        #pragma unroll
        for (int c = 0; c < 8; c++) {
            float4 g  = gr4[c];
            float4 rj = rs4[c];
            float4 dj = dv4[c];
            a[4 * c + 0] = (fmaf(-(1.0f / 32.0f), rj.x, g.x + base)) * (dv * dj.x);
            a[4 * c + 1] = (fmaf(-(1.0f / 32.0f), rj.y, g.y + base)) * (dv * dj.y);
            a[4 * c + 2] = (fmaf(-(1.0f / 32.0f), rj.z, g.z + base)) * (dv * dj.z);
            a[4 * c + 3] = (fmaf(-(1.0f / 32.0f), rj.w, g.w + base)) * (dv * dj.w);
        }
    }

    // ================= Householder tridiagonalization (rolled) ==============
    #pragma unroll 1
    for (int k = 0; k < 30; k++) {
        const int m = k + 1;
        float* xcur = xSh + ((k & 1) << 5);
        const float4* xc4 = reinterpret_cast<const float4*>(xcur);
        const float4* p4  = reinterpret_cast<const float4*>(pSh);

        // R0: parallel publish of masked column k
        float myx = sel32(a, k);
        myx = (lane > k) ? myx : 0.f;
        xcur[lane] = myx;
        __syncwarp();

        // R1: sigma/alpha/beta (redundant, identical across lanes)
        float s0 = 0.f, s1 = 0.f, s2 = 0.f, s3 = 0.f;
        #pragma unroll
        for (int c = 0; c < 8; c++) {
            float4 v = xc4[c];
            s0 = fmaf(v.x, v.x, s0); s1 = fmaf(v.y, v.y, s1);
            s2 = fmaf(v.z, v.z, s2); s3 = fmaf(v.w, v.w, s3);
        }
        float sig = (s0 + s1) + (s2 + s3);
        float x0  = xcur[m];
        float nrm = sqrtf(sig);
        float alpha = -copysignf(nrm, x0);
        float beta  = (sig > 1e-30f) ? __fdividef(1.f, sig + fabsf(x0) * nrm) : 0.f;
        if (lane == 0) { e2S[k] = alpha * alpha; eaS[k] = fabsf(alpha); }
        __syncwarp();

        // R2: patch v_m
        if (lane == m) xcur[m] = x0 - alpha;
        __syncwarp();

        // R3: p = beta * (A v); stale rows (lane < m) masked
        float q0 = 0.f, q1 = 0.f, q2 = 0.f, q3 = 0.f;
        #pragma unroll
        for (int c = 0; c < 8; c++) {
            float4 v = xc4[c];
            q0 = fmaf(a[4 * c + 0], v.x, q0);
            q1 = fmaf(a[4 * c + 1], v.y, q1);
            q2 = fmaf(a[4 * c + 2], v.z, q2);
            q3 = fmaf(a[4 * c + 3], v.w, q3);
        }
        float p = ((q0 + q1) + (q2 + q3));
        p = (lane >= m) ? p * beta : 0.f;
        pSh[lane] = p;
        __syncwarp();

        // R4: vtp via butterfly; 2-FMA update
        float vi  = (lane == m) ? (x0 - alpha) : myx;   // myx=0 for lane<=k
        float vtp = wsum32(vi * p);
        float Kc  = 0.5f * beta * vtp;
        float ui  = fmaf(-2.f * Kc, vi, p);             // ui = p - 2*Kc*vi

        #pragma unroll
        for (int c = 0; c < 8; c++) {
            float4 vv = xc4[c];
            float4 pp = p4[c];
            a[4 * c + 0] = fmaf(-vi, pp.x, fmaf(-ui, vv.x, a[4 * c + 0]));
            a[4 * c + 1] = fmaf(-vi, pp.y, fmaf(-ui, vv.y, a[4 * c + 1]));
            a[4 * c + 2] = fmaf(-vi, pp.z, fmaf(-ui, vv.z, a[4 * c + 2]));
            a[4 * c + 3] = fmaf(-vi, pp.w, fmaf(-ui, vv.w, a[4 * c + 3]));
        }
        // next step writes the OTHER x buffer; pSh next write is 3 syncs away
    }
    {   // last offdiagonal e_30 = A[30][31]
        float e30 = __shfl_sync(FULLM, a[31], 30);
        if (lane == 0) {
            e2S[30] = e30 * e30; eaS[30] = fabsf(e30);
            e2S[31] = 0.f;       eaS[31] = 0.f;
        }
    }
    const float mydiag = sel32(a, lane);     // tridiagonal diagonal
    dS[lane] = mydiag;
    const float trace = wsum32(mydiag);      // trace(T) == trace(C)
    __syncwarp();

    // ================= multi-point Sturm bisection ==========================
    float eprev = (lane > 0) ? eaS[lane - 1] : 0.f;
    float rad   = eaS[lane] + eprev;
    float lo = wmin32(dS[lane] - rad);
    float hi = wmax32(dS[lane] + rad);

    // 3 targets x 10 lanes: ascending eigen indices 31 (e0), 24 (e7), 23 (e8).
    int g = lane / 10; if (g > 2) g = 2;
    const int mm = lane - g * 10;                // 0..9 (lanes 30,31 ignored)
    const int idx = (g == 0) ? 31 : (g == 1) ? 24 : 23;

    #pragma unroll 1
    for (int r = 0; r < 8; r++) {
        float w  = (hi - lo) * (1.0f / 11.0f);
        float xx = lo + w * (float)(mm + 1);
        int   cnt  = sturm32(dS, e2S, xx);
        unsigned bal = __ballot_sync(FULLM, cnt <= idx);
        unsigned gb  = (bal >> (g * 10)) & 0x3FFu;
        int mstar = 31 - __clz(gb);              // -1..9
        lo = lo + w * (float)(mstar + 1);
        hi = lo + w;
    }
    float lam = 0.5f * (lo + hi);
    float e0 = __shfl_sync(FULLM, lam, 0);
    float e7 = __shfl_sync(FULLM, lam, 10);
    float e8 = __shfl_sync(FULLM, lam, 20);

    if (lane == 0) {
        float gap   = e7 - e8;
        float decay = (e0 - e8) * (1.0f / 9.0f);
        float lmin  = e8 + 1e-8f;
        float topo  = gap / (decay + 1e-8f);
        if (topo < 0.f) topo = 0.f;
        float geo   = lmin / (trace + 1e-8f);
        float gcve  = topo + geo;
        out[b]         = gcve;   // gcve_scores
        out[n + b]     = 0.0f;   // fracture_scores
        out[2 * n + b] = gcve;   // total_pressure
    }
}

// ---------------------------------------------------------------------------
extern "C" void kernel_launch(void* const* d_in, const int* in_sizes, int n_in,
                              void* d_out, int out_size) {
    const float* h = (const float*)d_in[0];
    float* out = (float*)d_out;
    int n = out_size / 3;   // 32

    dim3 g1(NCH, BATCH);
    gram_kernel<<<g1, 544>>>(h);
    eig_kernel<<<148, 544>>>(out, n);   // blocks >= 32 exit immediately
}